// round 2
// baseline (speedup 1.0000x reference)
#include <cuda_runtime.h>
#include <math.h>

// Problem constants: B=4, C=1024, DK=1024, 3DK=3072, size = out_size/(B*DK)
#define BB 4
#define CC 1024
#define DK 1024
#define DK4 (DK / 4)          // 256 float4 per row
#define TDK 3072
#define NSEG 8
#define CSEG (CC / NSEG)      // 128
#define CHUNK 128
#define MAXCH 64
#define MAXLEN_PAD 8192

// -------- scratch (device globals) --------
__device__ float g_qkv_part[NSEG * BB * TDK];
__device__ float g_qkv[BB * TDK];               // q | k_new | v_new
__device__ float g_w[BB * MAXLEN_PAD];
__device__ float g_e[BB * MAXLEN_PAD];
__device__ float g_invD[BB * MAXLEN_PAD];
__device__ float g_P[BB * MAXCH * DK];          // chunk partial sums

// ---------------- K1: QKV projection partials ----------------
__global__ void k_proj_partial(const float* __restrict__ x,
                               const float* __restrict__ W, int S) {
    int jt  = blockIdx.x;
    int seg = blockIdx.y;
    int j   = jt * 128 + threadIdx.x;
    int c0  = seg * CSEG;

    __shared__ float xs[BB][CSEG];
    for (int i = threadIdx.x; i < BB * CSEG; i += 128) {
        int b = i / CSEG, cc = i % CSEG;
        xs[b][cc] = x[(size_t)b * S * CC + (size_t)(S - 1) * CC + c0 + cc];
    }
    __syncthreads();

    float a0 = 0.f, a1 = 0.f, a2 = 0.f, a3 = 0.f;
    const float* Wp = W + (size_t)c0 * TDK + j;
#pragma unroll 8
    for (int cc = 0; cc < CSEG; cc++) {
        float w = Wp[(size_t)cc * TDK];
        a0 += xs[0][cc] * w;
        a1 += xs[1][cc] * w;
        a2 += xs[2][cc] * w;
        a3 += xs[3][cc] * w;
    }
    g_qkv_part[(size_t)(seg * BB + 0) * TDK + j] = a0;
    g_qkv_part[(size_t)(seg * BB + 1) * TDK + j] = a1;
    g_qkv_part[(size_t)(seg * BB + 2) * TDK + j] = a2;
    g_qkv_part[(size_t)(seg * BB + 3) * TDK + j] = a3;
}

// ---------------- K1b: reduce partials + bias ----------------
__global__ void k_proj_reduce(const float* __restrict__ bias) {
    int idx = blockIdx.x * 256 + threadIdx.x;   // BB*TDK = 12288
    if (idx >= BB * TDK) return;
    int b = idx / TDK, j = idx % TDK;
    float s = bias[j];
#pragma unroll
    for (int seg = 0; seg < NSEG; seg++)
        s += g_qkv_part[(size_t)(seg * BB + b) * TDK + j];
    g_qkv[(size_t)b * TDK + j] = s;
}

// ---------------- K2: logits; each warp does 2 T rows ----------------
__global__ void k_logits(const float* __restrict__ kc, int ML, int size, int tok) {
    int b    = blockIdx.y;
    int warp = threadIdx.x >> 5;
    int lane = threadIdx.x & 31;
    int T0   = (blockIdx.x * 8 + warp) * 2;

    __shared__ float qs[DK];
    for (int i = threadIdx.x; i < DK; i += 256)
        qs[i] = g_qkv[(size_t)b * TDK + i];
    __syncthreads();

    if (T0 >= size) return;
    bool has2 = (T0 + 1) < size;
    const float* k0 = (T0 == tok)     ? (g_qkv + (size_t)b * TDK + DK)
                                      : (kc + ((size_t)b * ML + T0) * DK);
    const float* k1 = ((T0 + 1) == tok) ? (g_qkv + (size_t)b * TDK + DK)
                                        : (kc + ((size_t)b * ML + T0 + 1) * DK);
    float acc0 = 0.f, acc1 = 0.f;
#pragma unroll
    for (int i = 0; i < 8; i++) {
        float4 qv = *(const float4*)(qs + i * 128 + lane * 4);
        float4 a  = *(const float4*)(k0 + i * 128 + lane * 4);
        acc0 += a.x * qv.x + a.y * qv.y + a.z * qv.z + a.w * qv.w;
        if (has2) {
            float4 c = *(const float4*)(k1 + i * 128 + lane * 4);
            acc1 += c.x * qv.x + c.y * qv.y + c.z * qv.z + c.w * qv.w;
        }
    }
#pragma unroll
    for (int o = 16; o; o >>= 1) {
        acc0 += __shfl_xor_sync(0xFFFFFFFFu, acc0, o);
        acc1 += __shfl_xor_sync(0xFFFFFFFFu, acc1, o);
    }
    if (lane == 0) {
        g_w[(size_t)b * MAXLEN_PAD + T0] = acc0 * 0.03125f;
        if (has2) g_w[(size_t)b * MAXLEN_PAD + T0 + 1] = acc1 * 0.03125f;
    }
}

// ---------------- K3: softmax prefix scan, 1024 threads, float4 ----------------
// Assumes size <= 4096. grid B, block 1024.
__global__ void k_softmax_scan(int size) {
    int b   = blockIdx.x;
    int tid = threadIdx.x;
    int t0  = tid * 4;
    const float4* w4 = (const float4*)(g_w + (size_t)b * MAXLEN_PAD);
    float4* e4 = (float4*)(g_e + (size_t)b * MAXLEN_PAD);
    float4* d4 = (float4*)(g_invD + (size_t)b * MAXLEN_PAD);

    const float NEG = -3.4e38f;
    float4 w = make_float4(NEG, NEG, NEG, NEG);
    if (t0 + 3 < size) {
        w = w4[tid];
    } else if (t0 < size) {
        const float* wr = g_w + (size_t)b * MAXLEN_PAD;
        w.x = wr[t0];
        if (t0 + 1 < size) w.y = wr[t0 + 1];
        if (t0 + 2 < size) w.z = wr[t0 + 2];
    }

    // block max
    float m = fmaxf(fmaxf(w.x, w.y), fmaxf(w.z, w.w));
#pragma unroll
    for (int o = 16; o; o >>= 1) m = fmaxf(m, __shfl_xor_sync(0xFFFFFFFFu, m, o));
    __shared__ float sm[32];
    int wid = tid >> 5, lane = tid & 31;
    if (lane == 0) sm[wid] = m;
    __syncthreads();
    if (wid == 0) {
        float v = sm[lane];
#pragma unroll
        for (int o = 16; o; o >>= 1) v = fmaxf(v, __shfl_xor_sync(0xFFFFFFFFu, v, o));
        sm[lane] = v;
    }
    __syncthreads();
    float M = sm[0];
    __syncthreads();

    // exp
    float4 e;
    e.x = (t0     < size) ? __expf(w.x - M) : 0.f;
    e.y = (t0 + 1 < size) ? __expf(w.y - M) : 0.f;
    e.z = (t0 + 2 < size) ? __expf(w.z - M) : 0.f;
    e.w = (t0 + 3 < size) ? __expf(w.w - M) : 0.f;
    float ls = e.x + e.y + e.z + e.w;

    // inclusive block scan of ls
    float v = ls;
#pragma unroll
    for (int o = 1; o < 32; o <<= 1) {
        float u = __shfl_up_sync(0xFFFFFFFFu, v, o);
        if (lane >= o) v += u;
    }
    __shared__ float ws[32];
    if (lane == 31) ws[wid] = v;
    __syncthreads();
    if (wid == 0) {
        float u = ws[lane];
#pragma unroll
        for (int o = 1; o < 32; o <<= 1) {
            float p = __shfl_up_sync(0xFFFFFFFFu, u, o);
            if (lane >= o) u += p;
        }
        ws[lane] = u;
    }
    __syncthreads();
    float base = (wid > 0 ? ws[wid - 1] : 0.f) + (v - ls);  // exclusive

    float run = base;
    float4 d;
    run += e.x; d.x = 1.0f / run;
    run += e.y; d.y = 1.0f / run;
    run += e.z; d.z = 1.0f / run;
    run += e.w; d.w = 1.0f / run;

    e4[tid] = e;
    d4[tid] = d;
}

// ---------------- K4a: chunk partial vector sums (float4) ----------------
// grid (nch, B), block 256 (= DK4 threads)
__global__ void k_chunk_sums(const float4* __restrict__ vc4, int ML, int size, int tok) {
    int b  = blockIdx.y;
    int ch = blockIdx.x;
    int c4 = threadIdx.x;
    int t0 = ch * CHUNK;
    int t1 = min(t0 + CHUNK, size);

    __shared__ float es[CHUNK];
    if (threadIdx.x < CHUNK) {
        int t = t0 + threadIdx.x;
        es[threadIdx.x] = (t < size) ? g_e[(size_t)b * MAXLEN_PAD + t] : 0.f;
    }
    __syncthreads();

    const float4* vb = vc4 + (size_t)b * ML * DK4;
    float4 vnew = *(const float4*)(g_qkv + (size_t)b * TDK + 2 * DK + 4 * c4);
    float4 acc = make_float4(0.f, 0.f, 0.f, 0.f);
#pragma unroll 4
    for (int t = t0; t < t1; t++) {
        float4 v = (t == tok) ? vnew : vb[(size_t)t * DK4 + c4];
        float e = es[t - t0];
        acc.x += e * v.x; acc.y += e * v.y; acc.z += e * v.z; acc.w += e * v.w;
    }
    ((float4*)g_P)[((size_t)b * MAXCH + ch) * DK4 + c4] = acc;
}

// ---------------- K4b: final pass with inline chunk prefix ----------------
// grid (nch, B), block 256
__global__ void k_output(const float4* __restrict__ vc4, float4* __restrict__ out4,
                         int ML, int size, int tok) {
    int b  = blockIdx.y;
    int ch = blockIdx.x;
    int c4 = threadIdx.x;
    int t0 = ch * CHUNK;
    int t1 = min(t0 + CHUNK, size);

    __shared__ float es[CHUNK];
    __shared__ float ds[CHUNK];
    if (threadIdx.x < CHUNK) {
        int t = t0 + threadIdx.x;
        es[threadIdx.x] = (t < size) ? g_e[(size_t)b * MAXLEN_PAD + t] : 0.f;
        ds[threadIdx.x] = (t < size) ? g_invD[(size_t)b * MAXLEN_PAD + t] : 1.f;
    }

    // inline exclusive prefix over prior chunks (independent loads, MLP)
    const float4* P4 = (const float4*)g_P + (size_t)b * MAXCH * DK4 + c4;
    float4 acc = make_float4(0.f, 0.f, 0.f, 0.f);
#pragma unroll 8
    for (int p = 0; p < ch; p++) {
        float4 v = P4[(size_t)p * DK4];
        acc.x += v.x; acc.y += v.y; acc.z += v.z; acc.w += v.w;
    }
    __syncthreads();

    const float4* vb = vc4 + (size_t)b * ML * DK4;
    float4 vnew = *(const float4*)(g_qkv + (size_t)b * TDK + 2 * DK + 4 * c4);
#pragma unroll 4
    for (int t = t0; t < t1; t++) {
        float4 v = (t == tok) ? vnew : vb[(size_t)t * DK4 + c4];
        float e = es[t - t0];
        acc.x += e * v.x; acc.y += e * v.y; acc.z += e * v.z; acc.w += e * v.w;
        float d = ds[t - t0];
        float4 o = make_float4(acc.x * d, acc.y * d, acc.z * d, acc.w * d);
        __stcs(&out4[((size_t)b * size + t) * DK4 + c4], o);
    }
}

// ---------------- launch ----------------
extern "C" void kernel_launch(void* const* d_in, const int* in_sizes, int n_in,
                              void* d_out, int out_size) {
    const float* x    = (const float*)d_in[0];
    const float* W    = (const float*)d_in[1];
    const float* bias = (const float*)d_in[2];
    const float* kc   = (const float*)d_in[3];
    const float* vc   = (const float*)d_in[4];
    int S    = in_sizes[0] / (BB * CC);
    int ML   = in_sizes[3] / (BB * DK);
    int size = out_size / (BB * DK);
    int tok  = size - 1;
    int nch  = (size + CHUNK - 1) / CHUNK;

    k_proj_partial<<<dim3(TDK / 128, NSEG), 128>>>(x, W, S);
    k_proj_reduce<<<(BB * TDK + 255) / 256, 256>>>(bias);
    k_logits<<<dim3((size + 15) / 16, BB), 256>>>(kc, ML, size, tok);
    k_softmax_scan<<<BB, 1024>>>(size);
    k_chunk_sums<<<dim3(nch, BB), 256>>>((const float4*)vc, ML, size, tok);
    k_output<<<dim3(nch, BB), 256>>>((const float4*)vc, (float4*)d_out, ML, size, tok);
}

// round 3
// speedup vs baseline: 1.6376x; 1.6376x over previous
#include <cuda_runtime.h>
#include <math.h>

// Problem constants: B=4, C=1024, DK=1024, 3DK=3072, size = out_size/(B*DK)
#define BB 4
#define CC 1024
#define DK 1024
#define DK4 (DK / 4)          // 256 float4 per row
#define TDK 3072
#define NSEG 8
#define CSEG (CC / NSEG)      // 128
#define CHUNK 32
#define MAXCH 256             // 8192/32
#define MAXLEN_PAD 8192

// -------- scratch (device globals) --------
__device__ float g_qkv_part[NSEG * BB * TDK];
__device__ float g_qkv[BB * TDK];               // q | k_new | v_new
__device__ float g_w[BB * MAXLEN_PAD];
__device__ float g_e[BB * MAXLEN_PAD];
__device__ float g_invD[BB * MAXLEN_PAD];
__device__ float g_P[BB * MAXCH * DK];          // chunk partial sums (then exclusive prefix)

// ---------------- K1: QKV projection partials ----------------
__global__ void k_proj_partial(const float* __restrict__ x,
                               const float* __restrict__ W, int S) {
    int jt  = blockIdx.x;
    int seg = blockIdx.y;
    int j   = jt * 128 + threadIdx.x;
    int c0  = seg * CSEG;

    __shared__ float xs[BB][CSEG];
    for (int i = threadIdx.x; i < BB * CSEG; i += 128) {
        int b = i / CSEG, cc = i % CSEG;
        xs[b][cc] = x[(size_t)b * S * CC + (size_t)(S - 1) * CC + c0 + cc];
    }
    __syncthreads();

    float a0 = 0.f, a1 = 0.f, a2 = 0.f, a3 = 0.f;
    const float* Wp = W + (size_t)c0 * TDK + j;
#pragma unroll 8
    for (int cc = 0; cc < CSEG; cc++) {
        float w = Wp[(size_t)cc * TDK];
        a0 += xs[0][cc] * w;
        a1 += xs[1][cc] * w;
        a2 += xs[2][cc] * w;
        a3 += xs[3][cc] * w;
    }
    g_qkv_part[(size_t)(seg * BB + 0) * TDK + j] = a0;
    g_qkv_part[(size_t)(seg * BB + 1) * TDK + j] = a1;
    g_qkv_part[(size_t)(seg * BB + 2) * TDK + j] = a2;
    g_qkv_part[(size_t)(seg * BB + 3) * TDK + j] = a3;
}

// ---------------- K1b: reduce partials + bias ----------------
__global__ void k_proj_reduce(const float* __restrict__ bias) {
    int idx = blockIdx.x * 256 + threadIdx.x;   // BB*TDK = 12288
    if (idx >= BB * TDK) return;
    int b = idx / TDK, j = idx % TDK;
    float s = bias[j];
#pragma unroll
    for (int seg = 0; seg < NSEG; seg++)
        s += g_qkv_part[(size_t)(seg * BB + b) * TDK + j];
    g_qkv[(size_t)b * TDK + j] = s;
}

// ---------------- K2: logits, 1 T row per warp ----------------
__global__ void k_logits(const float* __restrict__ kc, int ML, int size, int tok) {
    int b    = blockIdx.y;
    int warp = threadIdx.x >> 5;
    int lane = threadIdx.x & 31;
    int T    = blockIdx.x * 8 + warp;

    __shared__ float qs[DK];
    for (int i = threadIdx.x; i < DK; i += 256)
        qs[i] = g_qkv[(size_t)b * TDK + i];
    __syncthreads();

    if (T >= size) return;
    const float* krow = (T == tok) ? (g_qkv + (size_t)b * TDK + DK)
                                   : (kc + ((size_t)b * ML + T) * DK);
    float acc = 0.f;
#pragma unroll
    for (int i = 0; i < 8; i++) {
        float4 kv = *(const float4*)(krow + i * 128 + lane * 4);
        float4 qv = *(const float4*)(qs + i * 128 + lane * 4);
        acc += kv.x * qv.x + kv.y * qv.y + kv.z * qv.z + kv.w * qv.w;
    }
#pragma unroll
    for (int o = 16; o; o >>= 1) acc += __shfl_xor_sync(0xFFFFFFFFu, acc, o);
    if (lane == 0) g_w[(size_t)b * MAXLEN_PAD + T] = acc * 0.03125f;
}

// ---------------- K3: softmax prefix scan, 1024 threads, float4 ----------------
__global__ void k_softmax_scan(int size) {
    int b   = blockIdx.x;
    int tid = threadIdx.x;
    int t0  = tid * 4;
    const float4* w4 = (const float4*)(g_w + (size_t)b * MAXLEN_PAD);
    float4* e4 = (float4*)(g_e + (size_t)b * MAXLEN_PAD);
    float4* d4 = (float4*)(g_invD + (size_t)b * MAXLEN_PAD);

    const float NEG = -3.4e38f;
    float4 w = make_float4(NEG, NEG, NEG, NEG);
    if (t0 + 3 < size) {
        w = w4[tid];
    } else if (t0 < size) {
        const float* wr = g_w + (size_t)b * MAXLEN_PAD;
        w.x = wr[t0];
        if (t0 + 1 < size) w.y = wr[t0 + 1];
        if (t0 + 2 < size) w.z = wr[t0 + 2];
    }

    float m = fmaxf(fmaxf(w.x, w.y), fmaxf(w.z, w.w));
#pragma unroll
    for (int o = 16; o; o >>= 1) m = fmaxf(m, __shfl_xor_sync(0xFFFFFFFFu, m, o));
    __shared__ float sm[32];
    int wid = tid >> 5, lane = tid & 31;
    if (lane == 0) sm[wid] = m;
    __syncthreads();
    if (wid == 0) {
        float v = sm[lane];
#pragma unroll
        for (int o = 16; o; o >>= 1) v = fmaxf(v, __shfl_xor_sync(0xFFFFFFFFu, v, o));
        sm[lane] = v;
    }
    __syncthreads();
    float M = sm[0];
    __syncthreads();

    float4 e;
    e.x = (t0     < size) ? __expf(w.x - M) : 0.f;
    e.y = (t0 + 1 < size) ? __expf(w.y - M) : 0.f;
    e.z = (t0 + 2 < size) ? __expf(w.z - M) : 0.f;
    e.w = (t0 + 3 < size) ? __expf(w.w - M) : 0.f;
    float ls = e.x + e.y + e.z + e.w;

    float v = ls;
#pragma unroll
    for (int o = 1; o < 32; o <<= 1) {
        float u = __shfl_up_sync(0xFFFFFFFFu, v, o);
        if (lane >= o) v += u;
    }
    __shared__ float ws[32];
    if (lane == 31) ws[wid] = v;
    __syncthreads();
    if (wid == 0) {
        float u = ws[lane];
#pragma unroll
        for (int o = 1; o < 32; o <<= 1) {
            float p = __shfl_up_sync(0xFFFFFFFFu, u, o);
            if (lane >= o) u += p;
        }
        ws[lane] = u;
    }
    __syncthreads();
    float base = (wid > 0 ? ws[wid - 1] : 0.f) + (v - ls);

    float run = base;
    float4 d;
    run += e.x; d.x = 1.0f / run;
    run += e.y; d.y = 1.0f / run;
    run += e.z; d.z = 1.0f / run;
    run += e.w; d.w = 1.0f / run;

    e4[tid] = e;
    d4[tid] = d;
}

// ---------------- K4a: chunk partial vector sums (float4, CHUNK=32) ----------------
// grid (nch, B), block 256 (one float4 channel per thread)
__global__ void k_chunk_sums(const float4* __restrict__ vc4, int ML, int size, int tok) {
    int b  = blockIdx.y;
    int ch = blockIdx.x;
    int c4 = threadIdx.x;
    int t0 = ch * CHUNK;
    int t1 = min(t0 + CHUNK, size);

    __shared__ float es[CHUNK];
    if (threadIdx.x < CHUNK) {
        int t = t0 + threadIdx.x;
        es[threadIdx.x] = (t < size) ? g_e[(size_t)b * MAXLEN_PAD + t] : 0.f;
    }
    __syncthreads();

    const float4* vb = vc4 + (size_t)b * ML * DK4;
    float4 vnew = *(const float4*)(g_qkv + (size_t)b * TDK + 2 * DK + 4 * c4);
    float4 acc = make_float4(0.f, 0.f, 0.f, 0.f);
#pragma unroll 4
    for (int t = t0; t < t1; t++) {
        float4 v = (t == tok) ? vnew : __ldg(&vb[(size_t)t * DK4 + c4]);
        float e = es[t - t0];
        acc.x += e * v.x; acc.y += e * v.y; acc.z += e * v.z; acc.w += e * v.w;
    }
    ((float4*)g_P)[((size_t)b * MAXCH + ch) * DK4 + c4] = acc;
}

// ---------------- K4b: parallel exclusive prefix over chunks ----------------
// grid (DK4, B), block 256 (one chunk index per thread), Hillis-Steele in smem
__global__ void k_chunk_prefix(int nch) {
    int b  = blockIdx.y;
    int c4 = blockIdx.x;
    int t  = threadIdx.x;
    float4* P4 = (float4*)g_P + (size_t)b * MAXCH * DK4 + c4;

    __shared__ float4 s[256];
    float4 v = (t < nch) ? P4[(size_t)t * DK4] : make_float4(0.f, 0.f, 0.f, 0.f);
    s[t] = v;
    __syncthreads();
#pragma unroll
    for (int off = 1; off < 256; off <<= 1) {
        float4 u = (t >= off) ? s[t - off] : make_float4(0.f, 0.f, 0.f, 0.f);
        __syncthreads();
        s[t].x += u.x; s[t].y += u.y; s[t].z += u.z; s[t].w += u.w;
        __syncthreads();
    }
    if (t < nch) {
        float4 excl = (t > 0) ? s[t - 1] : make_float4(0.f, 0.f, 0.f, 0.f);
        P4[(size_t)t * DK4] = excl;
    }
}

// ---------------- K4c: final pass, write outputs ----------------
// grid (nch, B), block 256
__global__ void k_output(const float4* __restrict__ vc4, float4* __restrict__ out4,
                         int ML, int size, int tok) {
    int b  = blockIdx.y;
    int ch = blockIdx.x;
    int c4 = threadIdx.x;
    int t0 = ch * CHUNK;
    int t1 = min(t0 + CHUNK, size);

    __shared__ float es[CHUNK];
    __shared__ float ds[CHUNK];
    if (threadIdx.x < CHUNK) {
        int t = t0 + threadIdx.x;
        es[threadIdx.x] = (t < size) ? g_e[(size_t)b * MAXLEN_PAD + t] : 0.f;
        ds[threadIdx.x] = (t < size) ? g_invD[(size_t)b * MAXLEN_PAD + t] : 1.f;
    }
    float4 acc = ((const float4*)g_P)[((size_t)b * MAXCH + ch) * DK4 + c4];
    __syncthreads();

    const float4* vb = vc4 + (size_t)b * ML * DK4;
    float4 vnew = *(const float4*)(g_qkv + (size_t)b * TDK + 2 * DK + 4 * c4);
#pragma unroll 4
    for (int t = t0; t < t1; t++) {
        float4 v = (t == tok) ? vnew : __ldg(&vb[(size_t)t * DK4 + c4]);
        float e = es[t - t0];
        acc.x += e * v.x; acc.y += e * v.y; acc.z += e * v.z; acc.w += e * v.w;
        float d = ds[t - t0];
        float4 o = make_float4(acc.x * d, acc.y * d, acc.z * d, acc.w * d);
        __stcs(&out4[((size_t)b * size + t) * DK4 + c4], o);
    }
}

// ---------------- launch ----------------
extern "C" void kernel_launch(void* const* d_in, const int* in_sizes, int n_in,
                              void* d_out, int out_size) {
    const float* x    = (const float*)d_in[0];
    const float* W    = (const float*)d_in[1];
    const float* bias = (const float*)d_in[2];
    const float* kc   = (const float*)d_in[3];
    const float* vc   = (const float*)d_in[4];
    int S    = in_sizes[0] / (BB * CC);
    int ML   = in_sizes[3] / (BB * DK);
    int size = out_size / (BB * DK);
    int tok  = size - 1;
    int nch  = (size + CHUNK - 1) / CHUNK;

    k_proj_partial<<<dim3(TDK / 128, NSEG), 128>>>(x, W, S);
    k_proj_reduce<<<(BB * TDK + 255) / 256, 256>>>(bias);
    k_logits<<<dim3((size + 7) / 8, BB), 256>>>(kc, ML, size, tok);
    k_softmax_scan<<<BB, 1024>>>(size);
    k_chunk_sums<<<dim3(nch, BB), 256>>>((const float4*)vc, ML, size, tok);
    k_chunk_prefix<<<dim3(DK4, BB), 256>>>(nch);
    k_output<<<dim3(nch, BB), 256>>>((const float4*)vc, (float4*)d_out, ML, size, tok);
}